// round 4
// baseline (speedup 1.0000x reference)
#include <cuda_runtime.h>
#include <math.h>

// Problem constants (fixed by the dataset)
#define NN   100000
#define EE   3200000
#define INF  256
#define HF   128
#define NHOPS 4

// ---------------- scratch (device globals: no allocation allowed) -----------
__device__ float g_hA[(size_t)NN * HF];   // ping
__device__ float g_hB[(size_t)NN * HF];   // pong
__device__ int   g_col[EE];               // CSR column (src node per edge)
__device__ float g_wgt[EE];               // precomputed dinv[src]*dinv[dst]
__device__ int   g_rowptr[NN + 1];
__device__ int   g_deg[NN];
__device__ int   g_cur[NN];
__device__ float g_dinv[NN];
__device__ int   g_bsum[128];
__device__ int   g_boff[128];

// ---------------- CSR build --------------------------------------------------
__global__ void zero_kernel() {
    int i = blockIdx.x * blockDim.x + threadIdx.x;
    if (i < NN) { g_deg[i] = 0; g_cur[i] = 0; }
}

__global__ void hist_kernel(const int* __restrict__ dst) {
    int e = blockIdx.x * blockDim.x + threadIdx.x;
    if (e < EE) atomicAdd(&g_deg[dst[e]], 1);
}

__global__ void dinv_kernel() {
    int i = blockIdx.x * blockDim.x + threadIdx.x;
    if (i < NN) g_dinv[i] = rsqrtf((float)g_deg[i] + 1.0f);  // +1 self loop
}

// exclusive scan of g_deg -> g_rowptr, 3 passes
__global__ void scan1_kernel() {
    __shared__ int sh[1024];
    int tid = threadIdx.x;
    int i = blockIdx.x * 1024 + tid;
    int v = (i < NN) ? g_deg[i] : 0;
    sh[tid] = v;
    __syncthreads();
    for (int off = 1; off < 1024; off <<= 1) {
        int t = (tid >= off) ? sh[tid - off] : 0;
        __syncthreads();
        sh[tid] += t;
        __syncthreads();
    }
    if (i < NN) g_rowptr[i] = sh[tid] - v;       // exclusive
    if (tid == 1023) g_bsum[blockIdx.x] = sh[1023];
}

__global__ void scan2_kernel(int nb) {
    if (threadIdx.x == 0 && blockIdx.x == 0) {
        int run = 0;
        for (int i = 0; i < nb; i++) { g_boff[i] = run; run += g_bsum[i]; }
    }
}

__global__ void scan3_kernel() {
    int tid = threadIdx.x;
    int i = blockIdx.x * 1024 + tid;
    if (i < NN) g_rowptr[i] += g_boff[blockIdx.x];
    if (i == 0) g_rowptr[NN] = EE;
}

__global__ void scatter_kernel(const int* __restrict__ src,
                               const int* __restrict__ dst) {
    int e = blockIdx.x * blockDim.x + threadIdx.x;
    if (e >= EE) return;
    int s = src[e], d = dst[e];
    int pos = g_rowptr[d] + atomicAdd(&g_cur[d], 1);
    g_col[pos] = s;
    g_wgt[pos] = g_dinv[s] * g_dinv[d];
}

// ---------------- hop-0 input GEMM: h = relu(X @ W0 + b0) -------------------
// BM=128, BN=128(=HF), BK=16, 256 threads, 8x8 register tile per thread.
__global__ void gemm_relu_kernel(const float* __restrict__ A,   // [NN, INF]
                                 const float* __restrict__ B,   // [INF, HF]
                                 const float* __restrict__ bias) // [HF]
{
    __shared__ float As[16][128];
    __shared__ float Bs[16][128];
    int tid = threadIdx.x;
    int blockRow = blockIdx.x * 128;
    int tx = tid & 15, ty = tid >> 4;   // 16x16 thread grid

    float acc[8][8];
#pragma unroll
    for (int i = 0; i < 8; i++)
#pragma unroll
        for (int j = 0; j < 8; j++) acc[i][j] = 0.f;

    for (int k0 = 0; k0 < INF; k0 += 16) {
        // A tile: 128 rows x 16 cols = 512 float4, 2 per thread, store transposed
#pragma unroll
        for (int l = 0; l < 2; l++) {
            int li = tid + l * 256;          // 0..511
            int r  = li >> 2;                // row in tile
            int c4 = li & 3;                 // float4 slot in 16 cols
            int grow = blockRow + r;
            float4 v = make_float4(0.f, 0.f, 0.f, 0.f);
            if (grow < NN)
                v = *(const float4*)(A + (size_t)grow * INF + k0 + c4 * 4);
            As[c4 * 4 + 0][r] = v.x;
            As[c4 * 4 + 1][r] = v.y;
            As[c4 * 4 + 2][r] = v.z;
            As[c4 * 4 + 3][r] = v.w;
        }
        // B tile: 16 rows x 128 cols = 512 float4, 2 per thread
#pragma unroll
        for (int l = 0; l < 2; l++) {
            int li = tid + l * 256;
            int r  = li >> 5;                // 0..15
            int c4 = li & 31;
            float4 v = *(const float4*)(B + (size_t)(k0 + r) * HF + c4 * 4);
            *(float4*)&Bs[r][c4 * 4] = v;
        }
        __syncthreads();
#pragma unroll
        for (int k = 0; k < 16; k++) {
            float a[8], b[8];
#pragma unroll
            for (int i = 0; i < 8; i++) a[i] = As[k][ty * 8 + i];
#pragma unroll
            for (int j = 0; j < 8; j++) b[j] = Bs[k][tx * 8 + j];
#pragma unroll
            for (int i = 0; i < 8; i++)
#pragma unroll
                for (int j = 0; j < 8; j++) acc[i][j] = fmaf(a[i], b[j], acc[i][j]);
        }
        __syncthreads();
    }
    // epilogue: bias + relu into g_hA
#pragma unroll
    for (int i = 0; i < 8; i++) {
        int grow = blockRow + ty * 8 + i;
        if (grow >= NN) continue;
#pragma unroll
        for (int j = 0; j < 8; j++) {
            int gcol = tx * 8 + j;
            g_hA[(size_t)grow * HF + gcol] = fmaxf(acc[i][j] + bias[gcol], 0.f);
        }
    }
}

// ---------------- fused hop kernel ------------------------------------------
// warp per dst node: GCN aggregate + bias + relu + attentive combine.
// sel: 0 = A->B, 1 = B->A, 2 = B->d_out
__global__ void hop_kernel(int sel, float* __restrict__ dout,
                           const float* __restrict__ biases, // [NHOPS, HF]
                           const float* __restrict__ Watt,   // [NHOPS, 2*HF]
                           const float* __restrict__ batt,   // [NHOPS]
                           int hop)
{
    int warp = (blockIdx.x * blockDim.x + threadIdx.x) >> 5;
    int lane = threadIdx.x & 31;
    if (warp >= NN) return;

    const float* hin  = (sel == 0) ? g_hA : g_hB;
    float*       hout = (sel == 0) ? g_hB : ((sel == 1) ? g_hA : dout);

    const float4* hin4 = (const float4*)hin;
    float4 hd = hin4[(size_t)warp * 32 + lane];

    float dv = g_dinv[warp];
    float d2 = dv * dv;
    float4 acc = make_float4(hd.x * d2, hd.y * d2, hd.z * d2, hd.w * d2);

    int beg = g_rowptr[warp], end = g_rowptr[warp + 1];
    for (int e0 = beg; e0 < end; e0 += 32) {
        int myE = e0 + lane;
        int   sl = 0; float wl = 0.f;
        if (myE < end) { sl = g_col[myE]; wl = g_wgt[myE]; }
        int m = min(32, end - e0);
        for (int j = 0; j < m; j++) {
            int   s = __shfl_sync(0xffffffffu, sl, j);
            float w = __shfl_sync(0xffffffffu, wl, j);
            float4 hs = hin4[(size_t)s * 32 + lane];
            acc.x = fmaf(w, hs.x, acc.x);
            acc.y = fmaf(w, hs.y, acc.y);
            acc.z = fmaf(w, hs.z, acc.z);
            acc.w = fmaf(w, hs.w, acc.w);
        }
    }

    float4 b4 = ((const float4*)(biases + hop * HF))[lane];
    float4 hk;
    hk.x = fmaxf(acc.x + b4.x, 0.f);
    hk.y = fmaxf(acc.y + b4.y, 0.f);
    hk.z = fmaxf(acc.z + b4.z, 0.f);
    hk.w = fmaxf(acc.w + b4.w, 0.f);

    float4 wk = ((const float4*)(Watt + hop * 2 * HF))[lane];
    float4 wh = ((const float4*)(Watt + hop * 2 * HF + HF))[lane];
    float part = hk.x * wk.x + hk.y * wk.y + hk.z * wk.z + hk.w * wk.w
               + hd.x * wh.x + hd.y * wh.y + hd.z * wh.z + hd.w * wh.w;
#pragma unroll
    for (int off = 16; off; off >>= 1)
        part += __shfl_xor_sync(0xffffffffu, part, off);

    float a = tanhf(part + batt[hop]);
    float4 o;
    o.x = a * hk.x + (1.f - a) * hd.x;
    o.y = a * hk.y + (1.f - a) * hd.y;
    o.z = a * hk.z + (1.f - a) * hd.z;
    o.w = a * hk.w + (1.f - a) * hd.w;
    ((float4*)hout)[(size_t)warp * 32 + lane] = o;
}

// ---------------- launch ------------------------------------------------------
extern "C" void kernel_launch(void* const* d_in, const int* in_sizes, int n_in,
                              void* d_out, int out_size)
{
    const int*   ei       = (const int*)d_in[0];     // [2, E]
    const float* features = (const float*)d_in[1];   // [N, 256]
    const float* W0       = (const float*)d_in[2];   // [256, 128]
    const float* b0       = (const float*)d_in[3];   // [128]
    const float* biases   = (const float*)d_in[4];   // [4, 128]
    const float* Watt     = (const float*)d_in[5];   // [4, 256]
    const float* batt     = (const float*)d_in[6];   // [4]
    float* out = (float*)d_out;

    const int* src = ei;
    const int* dst = ei + EE;

    const int TB = 256;
    int nBlocksN = (NN + TB - 1) / TB;
    int nBlocksE = (EE + TB - 1) / TB;
    int nbScan   = (NN + 1023) / 1024;

    // CSR build (deterministic work, atomics only touch int counters)
    zero_kernel<<<nBlocksN, TB>>>();
    hist_kernel<<<nBlocksE, TB>>>(dst);
    dinv_kernel<<<nBlocksN, TB>>>();
    scan1_kernel<<<nbScan, 1024>>>();
    scan2_kernel<<<1, 32>>>(nbScan);
    scan3_kernel<<<nbScan, 1024>>>();
    scatter_kernel<<<nBlocksE, TB>>>(src, dst);

    // hop-0 input block: g_hA = relu(X @ W0 + b0)
    gemm_relu_kernel<<<(NN + 127) / 128, 256>>>(features, W0, b0);

    // 4 fused hops, ping-pong A/B, last hop writes d_out
    int hopBlocks = (NN * 32 + TB - 1) / TB;   // warp per node
    hop_kernel<<<hopBlocks, TB>>>(0, out, biases, Watt, batt, 0); // A -> B
    hop_kernel<<<hopBlocks, TB>>>(1, out, biases, Watt, batt, 1); // B -> A
    hop_kernel<<<hopBlocks, TB>>>(0, out, biases, Watt, batt, 2); // A -> B
    hop_kernel<<<hopBlocks, TB>>>(2, out, biases, Watt, batt, 3); // B -> out
}

// round 6
// speedup vs baseline: 1.0089x; 1.0089x over previous
#include <cuda_runtime.h>
#include <cuda_fp16.h>
#include <math.h>

// Problem constants (fixed by the dataset)
#define NN   100000
#define EE   3200000
#define INF  256
#define HF   128
#define NHOPS 4

// ---------------- scratch (device globals: no allocation allowed) -----------
__device__ float  g_hA[(size_t)NN * HF];    // fp32 ping
__device__ float  g_hB[(size_t)NN * HF];    // fp32 pong
__device__ __align__(16) __half g_fA[(size_t)NN * HF]; // fp16 shadow ping
__device__ __align__(16) __half g_fB[(size_t)NN * HF]; // fp16 shadow pong
__device__ int    g_col[EE];                // CSR column (src node per edge)
__device__ float  g_wgt[EE];                // precomputed dinv[src]*dinv[dst]
__device__ int    g_rowptr[NN + 1];
__device__ int    g_deg[NN];
__device__ int    g_cur[NN];
__device__ float  g_dinv[NN];
__device__ int    g_bsum[128];
__device__ int    g_boff[128];

// ---------------- small helpers ---------------------------------------------
__device__ __forceinline__ unsigned long long pk2(float x, float y) {
    unsigned long long r;
    asm("mov.b64 %0, {%1, %2};" : "=l"(r) : "f"(x), "f"(y));
    return r;
}
__device__ __forceinline__ void ffma2(unsigned long long& d,
                                      unsigned long long a,
                                      unsigned long long b) {
    asm("fma.rn.f32x2 %0, %1, %2, %3;" : "=l"(d) : "l"(a), "l"(b), "l"(d));
}
__device__ __forceinline__ float4 cvt16(uint2 v) {
    __half2 a = *reinterpret_cast<__half2*>(&v.x);
    __half2 b = *reinterpret_cast<__half2*>(&v.y);
    float2 fa = __half22float2(a);
    float2 fb = __half22float2(b);
    return make_float4(fa.x, fa.y, fb.x, fb.y);
}
__device__ __forceinline__ uint2 cvt32(float4 v) {
    __half2 a = __floats2half2_rn(v.x, v.y);
    __half2 b = __floats2half2_rn(v.z, v.w);
    uint2 r;
    r.x = *reinterpret_cast<unsigned*>(&a);
    r.y = *reinterpret_cast<unsigned*>(&b);
    return r;
}

// ---------------- CSR build --------------------------------------------------
__global__ void zero_kernel() {
    int i = blockIdx.x * blockDim.x + threadIdx.x;
    if (i < NN) { g_deg[i] = 0; g_cur[i] = 0; }
}

__global__ void hist_kernel(const int* __restrict__ dst) {
    int e = blockIdx.x * blockDim.x + threadIdx.x;
    if (e < EE) atomicAdd(&g_deg[dst[e]], 1);
}

__global__ void dinv_kernel() {
    int i = blockIdx.x * blockDim.x + threadIdx.x;
    if (i < NN) g_dinv[i] = rsqrtf((float)g_deg[i] + 1.0f);  // +1 self loop
}

__global__ void scan1_kernel() {
    __shared__ int sh[1024];
    int tid = threadIdx.x;
    int i = blockIdx.x * 1024 + tid;
    int v = (i < NN) ? g_deg[i] : 0;
    sh[tid] = v;
    __syncthreads();
    for (int off = 1; off < 1024; off <<= 1) {
        int t = (tid >= off) ? sh[tid - off] : 0;
        __syncthreads();
        sh[tid] += t;
        __syncthreads();
    }
    if (i < NN) g_rowptr[i] = sh[tid] - v;       // exclusive
    if (tid == 1023) g_bsum[blockIdx.x] = sh[1023];
}

__global__ void scan2_kernel(int nb) {
    if (threadIdx.x == 0 && blockIdx.x == 0) {
        int run = 0;
        for (int i = 0; i < nb; i++) { g_boff[i] = run; run += g_bsum[i]; }
    }
}

__global__ void scan3_kernel() {
    int tid = threadIdx.x;
    int i = blockIdx.x * 1024 + tid;
    if (i < NN) g_rowptr[i] += g_boff[blockIdx.x];
    if (i == 0) g_rowptr[NN] = EE;
}

__global__ void scatter_kernel(const int* __restrict__ src,
                               const int* __restrict__ dst) {
    int e = blockIdx.x * blockDim.x + threadIdx.x;
    if (e >= EE) return;
    int s = src[e], d = dst[e];
    int pos = g_rowptr[d] + atomicAdd(&g_cur[d], 1);
    g_col[pos] = s;
    g_wgt[pos] = g_dinv[s] * g_dinv[d];
}

// ---------------- hop-0 input GEMM: h = relu(X @ W0 + b0) -------------------
// BM=128, BN=128(=HF), BK=16, 256 threads, 8x8 per thread, FFMA2 (f32x2).
__global__ void gemm_relu_kernel(const float* __restrict__ A,    // [NN, INF]
                                 const float* __restrict__ B,    // [INF, HF]
                                 const float* __restrict__ bias) // [HF]
{
    __shared__ float As[16][128];
    __shared__ float Bs[16][128];
    int tid = threadIdx.x;
    int blockRow = blockIdx.x * 128;
    int tx = tid & 15, ty = tid >> 4;   // 16x16 thread grid

    unsigned long long acc2[8][4];      // 8 rows x 4 col-pairs (f32x2)
#pragma unroll
    for (int i = 0; i < 8; i++)
#pragma unroll
        for (int j = 0; j < 4; j++) acc2[i][j] = 0ull;

    for (int k0 = 0; k0 < INF; k0 += 16) {
        // A tile: 128 rows x 16 cols, stored transposed
#pragma unroll
        for (int l = 0; l < 2; l++) {
            int li = tid + l * 256;          // 0..511
            int r  = li >> 2;                // row in tile
            int c4 = li & 3;                 // float4 slot in 16 cols
            int grow = blockRow + r;
            float4 v = make_float4(0.f, 0.f, 0.f, 0.f);
            if (grow < NN)
                v = *(const float4*)(A + (size_t)grow * INF + k0 + c4 * 4);
            As[c4 * 4 + 0][r] = v.x;
            As[c4 * 4 + 1][r] = v.y;
            As[c4 * 4 + 2][r] = v.z;
            As[c4 * 4 + 3][r] = v.w;
        }
        // B tile: 16 rows x 128 cols
#pragma unroll
        for (int l = 0; l < 2; l++) {
            int li = tid + l * 256;
            int r  = li >> 5;                // 0..15
            int c4 = li & 31;
            float4 v = *(const float4*)(B + (size_t)(k0 + r) * HF + c4 * 4);
            *(float4*)&Bs[r][c4 * 4] = v;
        }
        __syncthreads();
#pragma unroll
        for (int k = 0; k < 16; k++) {
            // a values (8 floats), duplicated into f32x2
            float2 av[4];
#pragma unroll
            for (int i = 0; i < 4; i++)
                av[i] = *(const float2*)&As[k][ty * 8 + i * 2];
            unsigned long long ad[8];
#pragma unroll
            for (int i = 0; i < 4; i++) {
                ad[i * 2 + 0] = pk2(av[i].x, av[i].x);
                ad[i * 2 + 1] = pk2(av[i].y, av[i].y);
            }
            // b pairs (4 x f32x2)
            unsigned long long bp[4];
#pragma unroll
            for (int j = 0; j < 4; j++)
                bp[j] = *(const unsigned long long*)&Bs[k][tx * 8 + j * 2];
#pragma unroll
            for (int i = 0; i < 8; i++)
#pragma unroll
                for (int j = 0; j < 4; j++)
                    ffma2(acc2[i][j], ad[i], bp[j]);
        }
        __syncthreads();
    }
    // epilogue: bias + relu into g_hA (fp32) and g_fA (fp16 shadow)
#pragma unroll
    for (int i = 0; i < 8; i++) {
        int grow = blockRow + ty * 8 + i;
        if (grow >= NN) continue;
#pragma unroll
        for (int j = 0; j < 4; j++) {
            float2 v = *(float2*)&acc2[i][j];
            int gcol = tx * 8 + j * 2;
            float r0 = fmaxf(v.x + bias[gcol + 0], 0.f);
            float r1 = fmaxf(v.y + bias[gcol + 1], 0.f);
            g_hA[(size_t)grow * HF + gcol + 0] = r0;
            g_hA[(size_t)grow * HF + gcol + 1] = r1;
            __half2 h2 = __floats2half2_rn(r0, r1);
            *reinterpret_cast<__half2*>(&g_fA[(size_t)grow * HF + gcol]) = h2;
        }
    }
}

// ---------------- fused hop kernel ------------------------------------------
// warp per dst node: GCN aggregate (fp16 gather) + bias + relu + gated combine.
// sel: 0 = A->B, 1 = B->A, 2 = B->d_out (fp32 only)
__global__ void hop_kernel(int sel, float* __restrict__ dout,
                           const float* __restrict__ biases, // [NHOPS, HF]
                           const float* __restrict__ Watt,   // [NHOPS, 2*HF]
                           const float* __restrict__ batt,   // [NHOPS]
                           int hop)
{
    int warp = (blockIdx.x * blockDim.x + threadIdx.x) >> 5;
    int lane = threadIdx.x & 31;
    if (warp >= NN) return;

    const float*  hin   = (sel == 0) ? g_hA : g_hB;
    const __half* fin   = (sel == 0) ? g_fA : g_fB;
    float*        hout  = (sel == 0) ? g_hB : ((sel == 1) ? g_hA : dout);
    __half*       fout  = (sel == 0) ? g_fB : g_fA;   // unused when sel==2

    const float4* hin4 = (const float4*)hin;
    const uint2*  fin2 = (const uint2*)fin;           // 4 halves per lane

    float4 hd = hin4[(size_t)warp * 32 + lane];       // own row, fp32 (exact)

    float dv = g_dinv[warp];
    float d2 = dv * dv;
    float4 acc = make_float4(hd.x * d2, hd.y * d2, hd.z * d2, hd.w * d2);

    int beg = g_rowptr[warp], end = g_rowptr[warp + 1];
    for (int e0 = beg; e0 < end; e0 += 32) {
        int myE = e0 + lane;
        int   sl = 0; float wl = 0.f;
        if (myE < end) { sl = g_col[myE]; wl = g_wgt[myE]; }
        int m = min(32, end - e0);
        int j = 0;
        for (; j + 4 <= m; j += 4) {
            int   s0 = __shfl_sync(0xffffffffu, sl, j + 0);
            int   s1 = __shfl_sync(0xffffffffu, sl, j + 1);
            int   s2 = __shfl_sync(0xffffffffu, sl, j + 2);
            int   s3 = __shfl_sync(0xffffffffu, sl, j + 3);
            float w0 = __shfl_sync(0xffffffffu, wl, j + 0);
            float w1 = __shfl_sync(0xffffffffu, wl, j + 1);
            float w2 = __shfl_sync(0xffffffffu, wl, j + 2);
            float w3 = __shfl_sync(0xffffffffu, wl, j + 3);
            uint2 r0 = fin2[(size_t)s0 * 32 + lane];
            uint2 r1 = fin2[(size_t)s1 * 32 + lane];
            uint2 r2 = fin2[(size_t)s2 * 32 + lane];
            uint2 r3 = fin2[(size_t)s3 * 32 + lane];
            float4 f0 = cvt16(r0), f1 = cvt16(r1), f2 = cvt16(r2), f3 = cvt16(r3);
            acc.x = fmaf(w0, f0.x, acc.x); acc.y = fmaf(w0, f0.y, acc.y);
            acc.z = fmaf(w0, f0.z, acc.z); acc.w = fmaf(w0, f0.w, acc.w);
            acc.x = fmaf(w1, f1.x, acc.x); acc.y = fmaf(w1, f1.y, acc.y);
            acc.z = fmaf(w1, f1.z, acc.z); acc.w = fmaf(w1, f1.w, acc.w);
            acc.x = fmaf(w2, f2.x, acc.x); acc.y = fmaf(w2, f2.y, acc.y);
            acc.z = fmaf(w2, f2.z, acc.z); acc.w = fmaf(w2, f2.w, acc.w);
            acc.x = fmaf(w3, f3.x, acc.x); acc.y = fmaf(w3, f3.y, acc.y);
            acc.z = fmaf(w3, f3.z, acc.z); acc.w = fmaf(w3, f3.w, acc.w);
        }
        for (; j < m; j++) {
            int   s = __shfl_sync(0xffffffffu, sl, j);
            float w = __shfl_sync(0xffffffffu, wl, j);
            float4 f = cvt16(fin2[(size_t)s * 32 + lane]);
            acc.x = fmaf(w, f.x, acc.x);
            acc.y = fmaf(w, f.y, acc.y);
            acc.z = fmaf(w, f.z, acc.z);
            acc.w = fmaf(w, f.w, acc.w);
        }
    }

    float4 b4 = ((const float4*)(biases + hop * HF))[lane];
    float4 hk;
    hk.x = fmaxf(acc.x + b4.x, 0.f);
    hk.y = fmaxf(acc.y + b4.y, 0.f);
    hk.z = fmaxf(acc.z + b4.z, 0.f);
    hk.w = fmaxf(acc.w + b4.w, 0.f);

    float4 wk = ((const float4*)(Watt + hop * 2 * HF))[lane];
    float4 wh = ((const float4*)(Watt + hop * 2 * HF + HF))[lane];
    float part = hk.x * wk.x + hk.y * wk.y + hk.z * wk.z + hk.w * wk.w
               + hd.x * wh.x + hd.y * wh.y + hd.z * wh.z + hd.w * wh.w;
#pragma unroll
    for (int off = 16; off; off >>= 1)
        part += __shfl_xor_sync(0xffffffffu, part, off);

    float a = tanhf(part + batt[hop]);
    float4 o;
    o.x = a * hk.x + (1.f - a) * hd.x;
    o.y = a * hk.y + (1.f - a) * hd.y;
    o.z = a * hk.z + (1.f - a) * hd.z;
    o.w = a * hk.w + (1.f - a) * hd.w;
    ((float4*)hout)[(size_t)warp * 32 + lane] = o;
    if (sel != 2)
        ((uint2*)fout)[(size_t)warp * 32 + lane] = cvt32(o);
}

// ---------------- launch ------------------------------------------------------
extern "C" void kernel_launch(void* const* d_in, const int* in_sizes, int n_in,
                              void* d_out, int out_size)
{
    const int*   ei       = (const int*)d_in[0];     // [2, E]
    const float* features = (const float*)d_in[1];   // [N, 256]
    const float* W0       = (const float*)d_in[2];   // [256, 128]
    const float* b0       = (const float*)d_in[3];   // [128]
    const float* biases   = (const float*)d_in[4];   // [4, 128]
    const float* Watt     = (const float*)d_in[5];   // [4, 256]
    const float* batt     = (const float*)d_in[6];   // [4]
    float* out = (float*)d_out;

    const int* src = ei;
    const int* dst = ei + EE;

    const int TB = 256;
    int nBlocksN = (NN + TB - 1) / TB;
    int nBlocksE = (EE + TB - 1) / TB;
    int nbScan   = (NN + 1023) / 1024;

    // CSR build
    zero_kernel<<<nBlocksN, TB>>>();
    hist_kernel<<<nBlocksE, TB>>>(dst);
    dinv_kernel<<<nBlocksN, TB>>>();
    scan1_kernel<<<nbScan, 1024>>>();
    scan2_kernel<<<1, 32>>>(nbScan);
    scan3_kernel<<<nbScan, 1024>>>();
    scatter_kernel<<<nBlocksE, TB>>>(src, dst);

    // hop-0 input block: g_hA/g_fA = relu(X @ W0 + b0)
    gemm_relu_kernel<<<(NN + 127) / 128, 256>>>(features, W0, b0);

    // 4 fused hops, ping-pong, last hop writes d_out
    int hopBlocks = (NN * 32 + TB - 1) / TB;   // warp per node
    hop_kernel<<<hopBlocks, TB>>>(0, out, biases, Watt, batt, 0); // A -> B
    hop_kernel<<<hopBlocks, TB>>>(1, out, biases, Watt, batt, 1); // B -> A
    hop_kernel<<<hopBlocks, TB>>>(0, out, biases, Watt, batt, 2); // A -> B
    hop_kernel<<<hopBlocks, TB>>>(2, out, biases, Watt, batt, 3); // B -> out
}

// round 9
// speedup vs baseline: 1.1270x; 1.1171x over previous
#include <cuda_runtime.h>
#include <cuda_fp16.h>
#include <math.h>

// Problem constants (fixed by the dataset)
#define NN   100000
#define EE   3200000
#define INF  256
#define HF   128
#define NHOPS 4

// ---------------- scratch (device globals: no allocation allowed) -----------
__device__ float  g_hA[(size_t)NN * HF];    // fp32 ping
__device__ float  g_hB[(size_t)NN * HF];    // fp32 pong
__device__ __align__(16) __half g_fA[(size_t)NN * HF]; // fp16 shadow ping
__device__ __align__(16) __half g_fB[(size_t)NN * HF]; // fp16 shadow pong
__device__ int2   g_edge[EE];               // packed CSR: .x=src col, .y=weight bits
__device__ int    g_rowptr[NN + 1];
__device__ int    g_deg[NN];
__device__ int    g_cur[NN];
__device__ float  g_dinv[NN];
__device__ int    g_bsum[128];

// ---------------- small helpers ---------------------------------------------
__device__ __forceinline__ unsigned long long pk2(float x, float y) {
    unsigned long long r;
    asm("mov.b64 %0, {%1, %2};" : "=l"(r) : "f"(x), "f"(y));
    return r;
}
__device__ __forceinline__ void ffma2(unsigned long long& d,
                                      unsigned long long a,
                                      unsigned long long b) {
    asm("fma.rn.f32x2 %0, %1, %2, %3;" : "=l"(d) : "l"(a), "l"(b), "l"(d));
}
__device__ __forceinline__ float4 cvt16(uint2 v) {
    __half2 a = *reinterpret_cast<__half2*>(&v.x);
    __half2 b = *reinterpret_cast<__half2*>(&v.y);
    float2 fa = __half22float2(a);
    float2 fb = __half22float2(b);
    return make_float4(fa.x, fa.y, fb.x, fb.y);
}
__device__ __forceinline__ uint2 cvt32(float4 v) {
    __half2 a = __floats2half2_rn(v.x, v.y);
    __half2 b = __floats2half2_rn(v.z, v.w);
    uint2 r;
    r.x = *reinterpret_cast<unsigned*>(&a);
    r.y = *reinterpret_cast<unsigned*>(&b);
    return r;
}

// ---------------- CSR build --------------------------------------------------
__global__ void hist_kernel(const int* __restrict__ dst) {
    int e = blockIdx.x * blockDim.x + threadIdx.x;
    if (e < EE) atomicAdd(&g_deg[dst[e]], 1);
}

// block-wise exclusive scan of g_deg -> g_rowptr; also dinv + zero g_cur
__global__ void scan1_kernel() {
    __shared__ int sh[1024];
    int tid = threadIdx.x;
    int i = blockIdx.x * 1024 + tid;
    int v = (i < NN) ? g_deg[i] : 0;
    if (i < NN) {
        g_dinv[i] = rsqrtf((float)v + 1.0f);   // +1 self loop
        g_cur[i] = 0;
    }
    sh[tid] = v;
    __syncthreads();
    for (int off = 1; off < 1024; off <<= 1) {
        int t = (tid >= off) ? sh[tid - off] : 0;
        __syncthreads();
        sh[tid] += t;
        __syncthreads();
    }
    if (i < NN) g_rowptr[i] = sh[tid] - v;       // exclusive within block
    if (tid == 1023) g_bsum[blockIdx.x] = sh[1023];
}

// add block offsets (prefix of g_bsum) to rowptr
__global__ void scan23_kernel() {
    __shared__ int s_off;
    int tid = threadIdx.x;
    if (tid < 32) {
        int run = 0;
        for (int k = tid; k < (int)blockIdx.x; k += 32) run += g_bsum[k];
#pragma unroll
        for (int off = 16; off; off >>= 1)
            run += __shfl_xor_sync(0xffffffffu, run, off);
        if (tid == 0) s_off = run;
    }
    __syncthreads();
    int i = blockIdx.x * 1024 + tid;
    if (i < NN) g_rowptr[i] += s_off;
    if (i == 0) g_rowptr[NN] = EE;
}

__global__ void scatter_kernel(const int* __restrict__ src,
                               const int* __restrict__ dst) {
    int e = blockIdx.x * blockDim.x + threadIdx.x;
    if (e >= EE) return;
    int s = src[e], d = dst[e];
    int pos = g_rowptr[d] + atomicAdd(&g_cur[d], 1);
    float w = g_dinv[s] * g_dinv[d];
    g_edge[pos] = make_int2(s, __float_as_int(w));
}

// ---------------- hop-0 input GEMM: h = relu(X @ W0 + b0) -------------------
// BM=128, BN=128(=HF), BK=16, 256 threads, 8x8 per thread, FFMA2 (f32x2).
__global__ void gemm_relu_kernel(const float* __restrict__ A,    // [NN, INF]
                                 const float* __restrict__ B,    // [INF, HF]
                                 const float* __restrict__ bias) // [HF]
{
    __shared__ float As[16][128];
    __shared__ float Bs[16][128];
    int tid = threadIdx.x;
    int blockRow = blockIdx.x * 128;
    int tx = tid & 15, ty = tid >> 4;   // 16x16 thread grid

    unsigned long long acc2[8][4];      // 8 rows x 4 col-pairs (f32x2)
#pragma unroll
    for (int i = 0; i < 8; i++)
#pragma unroll
        for (int j = 0; j < 4; j++) acc2[i][j] = 0ull;

    for (int k0 = 0; k0 < INF; k0 += 16) {
#pragma unroll
        for (int l = 0; l < 2; l++) {
            int li = tid + l * 256;          // 0..511
            int r  = li >> 2;                // row in tile
            int c4 = li & 3;                 // float4 slot in 16 cols
            int grow = blockRow + r;
            float4 v = make_float4(0.f, 0.f, 0.f, 0.f);
            if (grow < NN)
                v = *(const float4*)(A + (size_t)grow * INF + k0 + c4 * 4);
            As[c4 * 4 + 0][r] = v.x;
            As[c4 * 4 + 1][r] = v.y;
            As[c4 * 4 + 2][r] = v.z;
            As[c4 * 4 + 3][r] = v.w;
        }
#pragma unroll
        for (int l = 0; l < 2; l++) {
            int li = tid + l * 256;
            int r  = li >> 5;                // 0..15
            int c4 = li & 31;
            float4 v = *(const float4*)(B + (size_t)(k0 + r) * HF + c4 * 4);
            *(float4*)&Bs[r][c4 * 4] = v;
        }
        __syncthreads();
#pragma unroll
        for (int k = 0; k < 16; k++) {
            float2 av[4];
#pragma unroll
            for (int i = 0; i < 4; i++)
                av[i] = *(const float2*)&As[k][ty * 8 + i * 2];
            unsigned long long ad[8];
#pragma unroll
            for (int i = 0; i < 4; i++) {
                ad[i * 2 + 0] = pk2(av[i].x, av[i].x);
                ad[i * 2 + 1] = pk2(av[i].y, av[i].y);
            }
            unsigned long long bp[4];
#pragma unroll
            for (int j = 0; j < 4; j++)
                bp[j] = *(const unsigned long long*)&Bs[k][tx * 8 + j * 2];
#pragma unroll
            for (int i = 0; i < 8; i++)
#pragma unroll
                for (int j = 0; j < 4; j++)
                    ffma2(acc2[i][j], ad[i], bp[j]);
        }
        __syncthreads();
    }
#pragma unroll
    for (int i = 0; i < 8; i++) {
        int grow = blockRow + ty * 8 + i;
        if (grow >= NN) continue;
#pragma unroll
        for (int j = 0; j < 4; j++) {
            float2 v = *(float2*)&acc2[i][j];
            int gcol = tx * 8 + j * 2;
            float r0 = fmaxf(v.x + bias[gcol + 0], 0.f);
            float r1 = fmaxf(v.y + bias[gcol + 1], 0.f);
            g_hA[(size_t)grow * HF + gcol + 0] = r0;
            g_hA[(size_t)grow * HF + gcol + 1] = r1;
            __half2 h2 = __floats2half2_rn(r0, r1);
            *reinterpret_cast<__half2*>(&g_fA[(size_t)grow * HF + gcol]) = h2;
        }
    }
}

// ---------------- fused hop kernel ------------------------------------------
// warp per dst node: GCN aggregate (fp16 gather) + bias + relu + gated combine.
// Branchless chunks: invalid lanes get (col=0, w=0) -> contribute exactly 0.
// sel: 0 = A->B, 1 = B->A, 2 = B->d_out (fp32 only)
__global__ void __launch_bounds__(256, 4)
hop_kernel(int sel, float* __restrict__ dout,
           const float* __restrict__ biases, // [NHOPS, HF]
           const float* __restrict__ Watt,   // [NHOPS, 2*HF]
           const float* __restrict__ batt,   // [NHOPS]
           int hop)
{
    int warp = (blockIdx.x * blockDim.x + threadIdx.x) >> 5;
    int lane = threadIdx.x & 31;
    if (warp >= NN) return;

    const float*  hin   = (sel == 0) ? g_hA : g_hB;
    const __half* fin   = (sel == 0) ? g_fA : g_fB;
    float*        hout  = (sel == 0) ? g_hB : ((sel == 1) ? g_hA : dout);
    __half*       fout  = (sel == 0) ? g_fB : g_fA;   // unused when sel==2

    const float4* hin4 = (const float4*)hin;
    const uint2*  fin2 = (const uint2*)fin;           // 4 halves per lane

    int rowbase = warp * 32;                          // 32-bit index math
    float4 hd = hin4[rowbase + lane];                 // own row, fp32 (exact)

    float dv = g_dinv[warp];
    float d2 = dv * dv;
    float4 acc = make_float4(hd.x * d2, hd.y * d2, hd.z * d2, hd.w * d2);

    int beg = g_rowptr[warp], end = g_rowptr[warp + 1];
    for (int c = beg; c < end; c += 32) {
        int2 ed = make_int2(0, 0);                    // dummy: row 0, weight 0
        if (c + lane < end) ed = g_edge[c + lane];
#pragma unroll
        for (int j = 0; j < 32; j += 4) {
            int   s0 = __shfl_sync(0xffffffffu, ed.x, j + 0);
            int   s1 = __shfl_sync(0xffffffffu, ed.x, j + 1);
            int   s2 = __shfl_sync(0xffffffffu, ed.x, j + 2);
            int   s3 = __shfl_sync(0xffffffffu, ed.x, j + 3);
            uint2 r0 = fin2[s0 * 32 + lane];
            uint2 r1 = fin2[s1 * 32 + lane];
            uint2 r2 = fin2[s2 * 32 + lane];
            uint2 r3 = fin2[s3 * 32 + lane];
            float w0 = __int_as_float(__shfl_sync(0xffffffffu, ed.y, j + 0));
            float w1 = __int_as_float(__shfl_sync(0xffffffffu, ed.y, j + 1));
            float w2 = __int_as_float(__shfl_sync(0xffffffffu, ed.y, j + 2));
            float w3 = __int_as_float(__shfl_sync(0xffffffffu, ed.y, j + 3));
            float4 f0 = cvt16(r0), f1 = cvt16(r1), f2 = cvt16(r2), f3 = cvt16(r3);
            acc.x = fmaf(w0, f0.x, acc.x); acc.y = fmaf(w0, f0.y, acc.y);
            acc.z = fmaf(w0, f0.z, acc.z); acc.w = fmaf(w0, f0.w, acc.w);
            acc.x = fmaf(w1, f1.x, acc.x); acc.y = fmaf(w1, f1.y, acc.y);
            acc.z = fmaf(w1, f1.z, acc.z); acc.w = fmaf(w1, f1.w, acc.w);
            acc.x = fmaf(w2, f2.x, acc.x); acc.y = fmaf(w2, f2.y, acc.y);
            acc.z = fmaf(w2, f2.z, acc.z); acc.w = fmaf(w2, f2.w, acc.w);
            acc.x = fmaf(w3, f3.x, acc.x); acc.y = fmaf(w3, f3.y, acc.y);
            acc.z = fmaf(w3, f3.z, acc.z); acc.w = fmaf(w3, f3.w, acc.w);
        }
    }

    float4 b4 = ((const float4*)(biases + hop * HF))[lane];
    float4 hk;
    hk.x = fmaxf(acc.x + b4.x, 0.f);
    hk.y = fmaxf(acc.y + b4.y, 0.f);
    hk.z = fmaxf(acc.z + b4.z, 0.f);
    hk.w = fmaxf(acc.w + b4.w, 0.f);

    float4 wk = ((const float4*)(Watt + hop * 2 * HF))[lane];
    float4 wh = ((const float4*)(Watt + hop * 2 * HF + HF))[lane];
    float part = hk.x * wk.x + hk.y * wk.y + hk.z * wk.z + hk.w * wk.w
               + hd.x * wh.x + hd.y * wh.y + hd.z * wh.z + hd.w * wh.w;
#pragma unroll
    for (int off = 16; off; off >>= 1)
        part += __shfl_xor_sync(0xffffffffu, part, off);

    float a = tanhf(part + batt[hop]);
    float4 o;
    o.x = a * hk.x + (1.f - a) * hd.x;
    o.y = a * hk.y + (1.f - a) * hd.y;
    o.z = a * hk.z + (1.f - a) * hd.z;
    o.w = a * hk.w + (1.f - a) * hd.w;
    ((float4*)hout)[rowbase + lane] = o;
    if (sel != 2)
        ((uint2*)fout)[rowbase + lane] = cvt32(o);
}

// ---------------- launch ------------------------------------------------------
extern "C" void kernel_launch(void* const* d_in, const int* in_sizes, int n_in,
                              void* d_out, int out_size)
{
    const int*   ei       = (const int*)d_in[0];     // [2, E]
    const float* features = (const float*)d_in[1];   // [N, 256]
    const float* W0       = (const float*)d_in[2];   // [256, 128]
    const float* b0       = (const float*)d_in[3];   // [128]
    const float* biases   = (const float*)d_in[4];   // [4, 128]
    const float* Watt     = (const float*)d_in[5];   // [4, 256]
    const float* batt     = (const float*)d_in[6];   // [4]
    float* out = (float*)d_out;

    const int* src = ei;
    const int* dst = ei + EE;

    const int TB = 256;
    int nBlocksE = (EE + TB - 1) / TB;
    int nbScan   = (NN + 1023) / 1024;

    // zero g_deg via memset node (keeps kernel-launch count low for ncu window)
    void* degPtr = nullptr;
    cudaGetSymbolAddress(&degPtr, g_deg);
    cudaMemsetAsync(degPtr, 0, NN * sizeof(int));

    // CSR build: hist -> scan(+dinv, zero cur) -> offsets -> scatter
    hist_kernel<<<nBlocksE, TB>>>(dst);
    scan1_kernel<<<nbScan, 1024>>>();
    scan23_kernel<<<nbScan, 1024>>>();
    scatter_kernel<<<nBlocksE, TB>>>(src, dst);

    // hop-0 input block: g_hA/g_fA = relu(X @ W0 + b0)
    gemm_relu_kernel<<<(NN + 127) / 128, 256>>>(features, W0, b0);

    // 4 fused hops, ping-pong, last hop writes d_out
    int hopBlocks = (NN * 32 + TB - 1) / TB;   // warp per node
    hop_kernel<<<hopBlocks, TB>>>(0, out, biases, Watt, batt, 0); // A -> B
    hop_kernel<<<hopBlocks, TB>>>(1, out, biases, Watt, batt, 1); // B -> A
    hop_kernel<<<hopBlocks, TB>>>(0, out, biases, Watt, batt, 2); // A -> B
    hop_kernel<<<hopBlocks, TB>>>(2, out, biases, Watt, batt, 3); // B -> out
}

// round 11
// speedup vs baseline: 1.4554x; 1.2914x over previous
#include <cuda_runtime.h>
#include <cuda_fp16.h>
#include <math.h>

// Problem constants (fixed by the dataset)
#define NN   100000
#define EE   3200000
#define INF  256
#define HF   128
#define NHOPS 4

// ---------------- scratch (device globals: no allocation allowed) -----------
__device__ float  g_hA[(size_t)NN * HF];    // fp32 ping
__device__ float  g_hB[(size_t)NN * HF];    // fp32 pong
// fp16 shadow holds dinv[n]*h[n]; row NN is a reserved all-zero dummy row
// (device globals are zero-initialized and row NN is never written).
__device__ __align__(16) __half g_fA[(size_t)(NN + 1) * HF];
__device__ __align__(16) __half g_fB[(size_t)(NN + 1) * HF];
__device__ int    g_col[EE];                // CSR column (src node per edge)
__device__ int    g_rowptr[NN + 1];
__device__ int    g_deg[NN];
__device__ int    g_cur[NN];
__device__ float  g_dinv[NN];
__device__ int    g_bsum[128];

// ---------------- small helpers ---------------------------------------------
__device__ __forceinline__ float4 cvt16(uint2 v) {
    __half2 a = *reinterpret_cast<__half2*>(&v.x);
    __half2 b = *reinterpret_cast<__half2*>(&v.y);
    float2 fa = __half22float2(a);
    float2 fb = __half22float2(b);
    return make_float4(fa.x, fa.y, fb.x, fb.y);
}
__device__ __forceinline__ unsigned tf32cvt(float v) {
    unsigned r;
    asm("cvt.rna.tf32.f32 %0, %1;" : "=r"(r) : "f"(v));
    return r;
}
__device__ __forceinline__ void mma_tf32(float* c, const unsigned* a, const unsigned* b) {
    asm volatile(
        "mma.sync.aligned.m16n8k8.row.col.f32.tf32.tf32.f32 "
        "{%0,%1,%2,%3},{%4,%5,%6,%7},{%8,%9},{%0,%1,%2,%3};"
        : "+f"(c[0]), "+f"(c[1]), "+f"(c[2]), "+f"(c[3])
        : "r"(a[0]), "r"(a[1]), "r"(a[2]), "r"(a[3]), "r"(b[0]), "r"(b[1]));
}
__device__ __forceinline__ void cp16(void* smem_ptr, const void* gmem_ptr, int sz) {
    unsigned sa = (unsigned)__cvta_generic_to_shared(smem_ptr);
    asm volatile("cp.async.cg.shared.global [%0], [%1], 16, %2;"
                 :: "r"(sa), "l"(gmem_ptr), "r"(sz));
}

// ---------------- CSR build --------------------------------------------------
__global__ void hist_kernel(const int* __restrict__ dst) {
    int e = blockIdx.x * blockDim.x + threadIdx.x;
    if (e < EE) atomicAdd(&g_deg[dst[e]], 1);
}

// block-wise exclusive scan of g_deg -> g_rowptr; also dinv + zero g_cur
__global__ void scan1_kernel() {
    __shared__ int sh[1024];
    int tid = threadIdx.x;
    int i = blockIdx.x * 1024 + tid;
    int v = (i < NN) ? g_deg[i] : 0;
    if (i < NN) {
        g_dinv[i] = rsqrtf((float)v + 1.0f);   // +1 self loop
        g_cur[i] = 0;
    }
    sh[tid] = v;
    __syncthreads();
    for (int off = 1; off < 1024; off <<= 1) {
        int t = (tid >= off) ? sh[tid - off] : 0;
        __syncthreads();
        sh[tid] += t;
        __syncthreads();
    }
    if (i < NN) g_rowptr[i] = sh[tid] - v;       // exclusive within block
    if (tid == 1023) g_bsum[blockIdx.x] = sh[1023];
}

__global__ void scan23_kernel() {
    __shared__ int s_off;
    int tid = threadIdx.x;
    if (tid < 32) {
        int run = 0;
        for (int k = tid; k < (int)blockIdx.x; k += 32) run += g_bsum[k];
#pragma unroll
        for (int off = 16; off; off >>= 1)
            run += __shfl_xor_sync(0xffffffffu, run, off);
        if (tid == 0) s_off = run;
    }
    __syncthreads();
    int i = blockIdx.x * 1024 + tid;
    if (i < NN) g_rowptr[i] += s_off;
    if (i == 0) g_rowptr[NN] = EE;
}

__global__ void scatter_kernel(const int* __restrict__ src,
                               const int* __restrict__ dst) {
    int e = blockIdx.x * blockDim.x + threadIdx.x;
    if (e >= EE) return;
    int s = src[e], d = dst[e];
    int pos = g_rowptr[d] + atomicAdd(&g_cur[d], 1);
    g_col[pos] = s;
}

// ---------------- hop-0 input GEMM (tf32 tensor cores) -----------------------
// h = relu(X @ W0 + b0). BM=128, BN=128(=HF), BK=16, 256 threads (8 warps).
// Warp w computes m32 x n64: mo = 32*(w>>1), no = 64*(w&1).
// cp.async double-buffered; tf32 m16n8k8 MMA, fp32 accumulate.
#define GAP 20      // As row pitch (floats): conflict-free a-frag lds
#define GBP 132     // Bs row pitch (floats): conflict-free b-frag lds
__global__ void __launch_bounds__(256)
gemm_relu_kernel(const float* __restrict__ A,    // [NN, INF]
                 const float* __restrict__ B,    // [INF, HF]
                 const float* __restrict__ bias) // [HF]
{
    __shared__ float As[2][128][GAP];
    __shared__ float Bs[2][16][GBP];
    __shared__ float sbias[HF];

    int tid  = threadIdx.x;
    int lane = tid & 31;
    int w    = tid >> 5;
    int mo   = (w >> 1) * 32;
    int no   = (w & 1) * 64;
    int blockRow = blockIdx.x * 128;

    if (tid < HF) sbias[tid] = bias[tid];

    float acc[2][8][4];
#pragma unroll
    for (int i = 0; i < 2; i++)
#pragma unroll
        for (int j = 0; j < 8; j++)
#pragma unroll
            for (int r = 0; r < 4; r++) acc[i][j][r] = 0.f;

    // ---- async tile loader: chunk c covers K rows [16c, 16c+16) ----
    auto load_chunk = [&](int c, int buf) {
        int k0 = c * 16;
        // A: 128 rows x 16 floats = 512 x 16B; q = tid + 256*i
#pragma unroll
        for (int i = 0; i < 2; i++) {
            int q   = tid + i * 256;
            int row = q >> 2;
            int kc  = (q & 3) * 4;
            int grow = blockRow + row;
            const float* gp = A + (size_t)min(grow, NN - 1) * INF + k0 + kc;
            cp16(&As[buf][row][kc], gp, (grow < NN) ? 16 : 0);
        }
        // B: 16 rows x 128 floats = 512 x 16B
#pragma unroll
        for (int i = 0; i < 2; i++) {
            int q   = tid + i * 256;
            int row = q >> 5;
            int nc  = (q & 31) * 4;
            cp16(&Bs[buf][row][nc], B + (size_t)(k0 + row) * HF + nc, 16);
        }
        asm volatile("cp.async.commit_group;");
    };

    load_chunk(0, 0);

    int r0 = lane >> 2, c0 = lane & 3;

    for (int c = 0; c < 16; c++) {
        int buf = c & 1;
        if (c + 1 < 16) {
            load_chunk(c + 1, (c + 1) & 1);
            asm volatile("cp.async.wait_group 1;");
        } else {
            asm volatile("cp.async.wait_group 0;");
        }
        __syncthreads();
#pragma unroll
        for (int ks = 0; ks < 2; ks++) {
            int kb = ks * 8;
            unsigned af[2][4];
#pragma unroll
            for (int i = 0; i < 2; i++) {
                int rbase = mo + 16 * i + r0;
                af[i][0] = tf32cvt(As[buf][rbase    ][kb + c0    ]);
                af[i][1] = tf32cvt(As[buf][rbase + 8][kb + c0    ]);
                af[i][2] = tf32cvt(As[buf][rbase    ][kb + c0 + 4]);
                af[i][3] = tf32cvt(As[buf][rbase + 8][kb + c0 + 4]);
            }
            unsigned bf[8][2];
#pragma unroll
            for (int j = 0; j < 8; j++) {
                int n = no + 8 * j + r0;
                bf[j][0] = tf32cvt(Bs[buf][kb + c0    ][n]);
                bf[j][1] = tf32cvt(Bs[buf][kb + c0 + 4][n]);
            }
#pragma unroll
            for (int i = 0; i < 2; i++)
#pragma unroll
                for (int j = 0; j < 8; j++)
                    mma_tf32(acc[i][j], af[i], bf[j]);
        }
        __syncthreads();
    }

    // ---- epilogue: bias + relu -> g_hA (fp32), dinv-scaled fp16 -> g_fA ----
#pragma unroll
    for (int i = 0; i < 2; i++) {
        int row_lo = blockRow + mo + 16 * i + r0;
#pragma unroll
        for (int rr = 0; rr < 2; rr++) {
            int row = row_lo + 8 * rr;
            if (row >= NN) continue;
            float dv = g_dinv[row];
#pragma unroll
            for (int j = 0; j < 8; j++) {
                int col = no + 8 * j + 2 * c0;
                float v0 = fmaxf(acc[i][j][2 * rr + 0] + sbias[col + 0], 0.f);
                float v1 = fmaxf(acc[i][j][2 * rr + 1] + sbias[col + 1], 0.f);
                *(float2*)&g_hA[(size_t)row * HF + col] = make_float2(v0, v1);
                __half2 h2 = __floats2half2_rn(dv * v0, dv * v1);
                *reinterpret_cast<__half2*>(&g_fA[(size_t)row * HF + col]) = h2;
            }
        }
    }
}

// ---------------- fused hop kernel ------------------------------------------
// warp per dst node. fp16 shadow stores p[n] = dinv[n]*h[n], so
//   agg[d] = dinv[d] * sum_{s in N(d)} p[s] + dinv[d]^2 * h[d]
// Branchless chunks: invalid lanes point at zero row NN.
// sel: 0 = A->B, 1 = B->A, 2 = B->d_out (fp32 only)
__global__ void __launch_bounds__(256, 4)
hop_kernel(int sel, float* __restrict__ dout,
           const float* __restrict__ biases, // [NHOPS, HF]
           const float* __restrict__ Watt,   // [NHOPS, 2*HF]
           const float* __restrict__ batt,   // [NHOPS]
           int hop)
{
    int warp = (blockIdx.x * blockDim.x + threadIdx.x) >> 5;
    int lane = threadIdx.x & 31;
    if (warp >= NN) return;

    const float*  hin   = (sel == 0) ? g_hA : g_hB;
    const __half* fin   = (sel == 0) ? g_fA : g_fB;
    float*        hout  = (sel == 0) ? g_hB : ((sel == 1) ? g_hA : dout);
    __half*       fout  = (sel == 0) ? g_fB : g_fA;   // unused when sel==2

    const float4* hin4 = (const float4*)hin;
    const uint2*  fin2 = (const uint2*)fin;           // 4 halves per lane

    int rowbase = warp * 32;                          // 32-bit index math
    float4 hd = hin4[rowbase + lane];                 // own row, fp32 (exact)

    float dv = g_dinv[warp];
    float d2 = dv * dv;
    float4 acc = make_float4(0.f, 0.f, 0.f, 0.f);     // sum of p[s]

    int beg = g_rowptr[warp], end = g_rowptr[warp + 1];
    for (int c = beg; c < end; c += 32) {
        int ed = NN;                                  // dummy -> zero row
        if (c + lane < end) ed = g_col[c + lane];
#pragma unroll
        for (int j = 0; j < 32; j += 4) {
            int s0 = __shfl_sync(0xffffffffu, ed, j + 0);
            int s1 = __shfl_sync(0xffffffffu, ed, j + 1);
            int s2 = __shfl_sync(0xffffffffu, ed, j + 2);
            int s3 = __shfl_sync(0xffffffffu, ed, j + 3);
            uint2 r0 = fin2[s0 * 32 + lane];
            uint2 r1 = fin2[s1 * 32 + lane];
            uint2 r2 = fin2[s2 * 32 + lane];
            uint2 r3 = fin2[s3 * 32 + lane];
            float4 f0 = cvt16(r0), f1 = cvt16(r1), f2 = cvt16(r2), f3 = cvt16(r3);
            acc.x += f0.x + f1.x + f2.x + f3.x;
            acc.y += f0.y + f1.y + f2.y + f3.y;
            acc.z += f0.z + f1.z + f2.z + f3.z;
            acc.w += f0.w + f1.w + f2.w + f3.w;
        }
    }

    float4 b4 = ((const float4*)(biases + hop * HF))[lane];
    float4 hk;
    hk.x = fmaxf(fmaf(dv, acc.x, fmaf(d2, hd.x, b4.x)), 0.f);
    hk.y = fmaxf(fmaf(dv, acc.y, fmaf(d2, hd.y, b4.y)), 0.f);
    hk.z = fmaxf(fmaf(dv, acc.z, fmaf(d2, hd.z, b4.z)), 0.f);
    hk.w = fmaxf(fmaf(dv, acc.w, fmaf(d2, hd.w, b4.w)), 0.f);

    float4 wk = ((const float4*)(Watt + hop * 2 * HF))[lane];
    float4 wh = ((const float4*)(Watt + hop * 2 * HF + HF))[lane];
    float part = hk.x * wk.x + hk.y * wk.y + hk.z * wk.z + hk.w * wk.w
               + hd.x * wh.x + hd.y * wh.y + hd.z * wh.z + hd.w * wh.w;
#pragma unroll
    for (int off = 16; off; off >>= 1)
        part += __shfl_xor_sync(0xffffffffu, part, off);

    float a = tanhf(part + batt[hop]);
    float4 o;
    o.x = a * hk.x + (1.f - a) * hd.x;
    o.y = a * hk.y + (1.f - a) * hd.y;
    o.z = a * hk.z + (1.f - a) * hd.z;
    o.w = a * hk.w + (1.f - a) * hd.w;
    ((float4*)hout)[rowbase + lane] = o;
    if (sel != 2) {
        __half2 p0 = __floats2half2_rn(dv * o.x, dv * o.y);
        __half2 p1 = __floats2half2_rn(dv * o.z, dv * o.w);
        uint2 pk;
        pk.x = *reinterpret_cast<unsigned*>(&p0);
        pk.y = *reinterpret_cast<unsigned*>(&p1);
        ((uint2*)fout)[rowbase + lane] = pk;
    }
}

// ---------------- launch ------------------------------------------------------
extern "C" void kernel_launch(void* const* d_in, const int* in_sizes, int n_in,
                              void* d_out, int out_size)
{
    const int*   ei       = (const int*)d_in[0];     // [2, E]
    const float* features = (const float*)d_in[1];   // [N, 256]
    const float* W0       = (const float*)d_in[2];   // [256, 128]
    const float* b0       = (const float*)d_in[3];   // [128]
    const float* biases   = (const float*)d_in[4];   // [4, 128]
    const float* Watt     = (const float*)d_in[5];   // [4, 256]
    const float* batt     = (const float*)d_in[6];   // [4]
    float* out = (float*)d_out;

    const int* src = ei;
    const int* dst = ei + EE;

    const int TB = 256;
    int nBlocksE = (EE + TB - 1) / TB;
    int nbScan   = (NN + 1023) / 1024;

    // zero g_deg via memset node
    void* degPtr = nullptr;
    cudaGetSymbolAddress(&degPtr, g_deg);
    cudaMemsetAsync(degPtr, 0, NN * sizeof(int));

    // CSR build: hist -> scan(+dinv, zero cur) -> offsets -> scatter
    hist_kernel<<<nBlocksE, TB>>>(dst);
    scan1_kernel<<<nbScan, 1024>>>();
    scan23_kernel<<<nbScan, 1024>>>();
    scatter_kernel<<<nBlocksE, TB>>>(src, dst);

    // hop-0 input block (needs g_dinv from scan1): g_hA/g_fA
    gemm_relu_kernel<<<(NN + 127) / 128, 256>>>(features, W0, b0);

    // 4 fused hops, ping-pong, last hop writes d_out
    int hopBlocks = (NN * 32 + TB - 1) / TB;   // warp per node
    hop_kernel<<<hopBlocks, TB>>>(0, out, biases, Watt, batt, 0); // A -> B
    hop_kernel<<<hopBlocks, TB>>>(1, out, biases, Watt, batt, 1); // B -> A
    hop_kernel<<<hopBlocks, TB>>>(0, out, biases, Watt, batt, 2); // A -> B
    hop_kernel<<<hopBlocks, TB>>>(2, out, biases, Watt, batt, 3); // B -> out
}

// round 12
// speedup vs baseline: 1.6051x; 1.1028x over previous
#include <cuda_runtime.h>
#include <cuda_fp16.h>
#include <math.h>

// Problem constants (fixed by the dataset)
#define NN   100000
#define EE   3200000
#define INF  256
#define HF   128
#define NHOPS 4

// ---------------- scratch (device globals: no allocation allowed) -----------
__device__ float  g_hA[(size_t)NN * HF];    // fp32 ping
__device__ float  g_hB[(size_t)NN * HF];    // fp32 pong
// fp16 shadow holds dinv[n]*h[n]; row NN is a reserved all-zero dummy row
// (device globals are zero-initialized and row NN is never written).
__device__ __align__(16) __half g_fA[(size_t)(NN + 1) * HF];
__device__ __align__(16) __half g_fB[(size_t)(NN + 1) * HF];
__device__ int    g_col[EE];                // CSR column (src node per edge)
__device__ int    g_rowptr[NN + 1];
__device__ int    g_deg[NN];
__device__ int    g_cur[NN];                // running write cursor (starts at rowptr)
__device__ float  g_dinv[NN];
__device__ int    g_bsum[128];

// ---------------- small helpers ---------------------------------------------
__device__ __forceinline__ float4 cvt16(uint2 v) {
    __half2 a = *reinterpret_cast<__half2*>(&v.x);
    __half2 b = *reinterpret_cast<__half2*>(&v.y);
    float2 fa = __half22float2(a);
    float2 fb = __half22float2(b);
    return make_float4(fa.x, fa.y, fb.x, fb.y);
}
__device__ __forceinline__ unsigned tf32cvt(float v) {
    unsigned r;
    asm("cvt.rna.tf32.f32 %0, %1;" : "=r"(r) : "f"(v));
    return r;
}
__device__ __forceinline__ void mma_tf32(float* c, const unsigned* a, const unsigned* b) {
    asm volatile(
        "mma.sync.aligned.m16n8k8.row.col.f32.tf32.tf32.f32 "
        "{%0,%1,%2,%3},{%4,%5,%6,%7},{%8,%9},{%0,%1,%2,%3};"
        : "+f"(c[0]), "+f"(c[1]), "+f"(c[2]), "+f"(c[3])
        : "r"(a[0]), "r"(a[1]), "r"(a[2]), "r"(a[3]), "r"(b[0]), "r"(b[1]));
}
__device__ __forceinline__ void cp16(void* smem_ptr, const void* gmem_ptr, int sz) {
    unsigned sa = (unsigned)__cvta_generic_to_shared(smem_ptr);
    asm volatile("cp.async.cg.shared.global [%0], [%1], 16, %2;"
                 :: "r"(sa), "l"(gmem_ptr), "r"(sz));
}

// ---------------- CSR build --------------------------------------------------
__global__ void hist_kernel(const int* __restrict__ dst) {
    int e = blockIdx.x * blockDim.x + threadIdx.x;
    if (e < EE) atomicAdd(&g_deg[dst[e]], 1);
}

// block-wise exclusive scan of g_deg -> g_rowptr; also dinv
__global__ void scan1_kernel() {
    __shared__ int sh[1024];
    int tid = threadIdx.x;
    int i = blockIdx.x * 1024 + tid;
    int v = (i < NN) ? g_deg[i] : 0;
    if (i < NN) g_dinv[i] = rsqrtf((float)v + 1.0f);   // +1 self loop
    sh[tid] = v;
    __syncthreads();
    for (int off = 1; off < 1024; off <<= 1) {
        int t = (tid >= off) ? sh[tid - off] : 0;
        __syncthreads();
        sh[tid] += t;
        __syncthreads();
    }
    if (i < NN) g_rowptr[i] = sh[tid] - v;       // exclusive within block
    if (tid == 1023) g_bsum[blockIdx.x] = sh[1023];
}

// add block offsets; also seed g_cur with the final rowptr
__global__ void scan23_kernel() {
    __shared__ int s_off;
    int tid = threadIdx.x;
    if (tid < 32) {
        int run = 0;
        for (int k = tid; k < (int)blockIdx.x; k += 32) run += g_bsum[k];
#pragma unroll
        for (int off = 16; off; off >>= 1)
            run += __shfl_xor_sync(0xffffffffu, run, off);
        if (tid == 0) s_off = run;
    }
    __syncthreads();
    int i = blockIdx.x * 1024 + tid;
    if (i < NN) {
        int rp = g_rowptr[i] + s_off;
        g_rowptr[i] = rp;
        g_cur[i] = rp;                           // scatter cursor
    }
    if (i == 0) g_rowptr[NN] = EE;
}

__global__ void scatter_kernel(const int* __restrict__ src,
                               const int* __restrict__ dst) {
    int e = blockIdx.x * blockDim.x + threadIdx.x;
    if (e >= EE) return;
    int pos = atomicAdd(&g_cur[dst[e]], 1);
    g_col[pos] = src[e];
}

// ---------------- hop-0 input GEMM (tf32 tensor cores) -----------------------
#define GAP 20      // As row pitch (floats)
#define GBP 132     // Bs row pitch (floats)
__global__ void __launch_bounds__(256)
gemm_relu_kernel(const float* __restrict__ A,    // [NN, INF]
                 const float* __restrict__ B,    // [INF, HF]
                 const float* __restrict__ bias) // [HF]
{
    __shared__ float As[2][128][GAP];
    __shared__ float Bs[2][16][GBP];
    __shared__ float sbias[HF];

    int tid  = threadIdx.x;
    int lane = tid & 31;
    int w    = tid >> 5;
    int mo   = (w >> 1) * 32;
    int no   = (w & 1) * 64;
    int blockRow = blockIdx.x * 128;

    if (tid < HF) sbias[tid] = bias[tid];

    float acc[2][8][4];
#pragma unroll
    for (int i = 0; i < 2; i++)
#pragma unroll
        for (int j = 0; j < 8; j++)
#pragma unroll
            for (int r = 0; r < 4; r++) acc[i][j][r] = 0.f;

    auto load_chunk = [&](int c, int buf) {
        int k0 = c * 16;
#pragma unroll
        for (int i = 0; i < 2; i++) {
            int q   = tid + i * 256;
            int row = q >> 2;
            int kc  = (q & 3) * 4;
            int grow = blockRow + row;
            const float* gp = A + (size_t)min(grow, NN - 1) * INF + k0 + kc;
            cp16(&As[buf][row][kc], gp, (grow < NN) ? 16 : 0);
        }
#pragma unroll
        for (int i = 0; i < 2; i++) {
            int q   = tid + i * 256;
            int row = q >> 5;
            int nc  = (q & 31) * 4;
            cp16(&Bs[buf][row][nc], B + (size_t)(k0 + row) * HF + nc, 16);
        }
        asm volatile("cp.async.commit_group;");
    };

    load_chunk(0, 0);

    int r0 = lane >> 2, c0 = lane & 3;

    for (int c = 0; c < 16; c++) {
        int buf = c & 1;
        if (c + 1 < 16) {
            load_chunk(c + 1, (c + 1) & 1);
            asm volatile("cp.async.wait_group 1;");
        } else {
            asm volatile("cp.async.wait_group 0;");
        }
        __syncthreads();
#pragma unroll
        for (int ks = 0; ks < 2; ks++) {
            int kb = ks * 8;
            unsigned af[2][4];
#pragma unroll
            for (int i = 0; i < 2; i++) {
                int rbase = mo + 16 * i + r0;
                af[i][0] = tf32cvt(As[buf][rbase    ][kb + c0    ]);
                af[i][1] = tf32cvt(As[buf][rbase + 8][kb + c0    ]);
                af[i][2] = tf32cvt(As[buf][rbase    ][kb + c0 + 4]);
                af[i][3] = tf32cvt(As[buf][rbase + 8][kb + c0 + 4]);
            }
            unsigned bf[8][2];
#pragma unroll
            for (int j = 0; j < 8; j++) {
                int n = no + 8 * j + r0;
                bf[j][0] = tf32cvt(Bs[buf][kb + c0    ][n]);
                bf[j][1] = tf32cvt(Bs[buf][kb + c0 + 4][n]);
            }
#pragma unroll
            for (int i = 0; i < 2; i++)
#pragma unroll
                for (int j = 0; j < 8; j++)
                    mma_tf32(acc[i][j], af[i], bf[j]);
        }
        __syncthreads();
    }

#pragma unroll
    for (int i = 0; i < 2; i++) {
        int row_lo = blockRow + mo + 16 * i + r0;
#pragma unroll
        for (int rr = 0; rr < 2; rr++) {
            int row = row_lo + 8 * rr;
            if (row >= NN) continue;
            float dv = g_dinv[row];
#pragma unroll
            for (int j = 0; j < 8; j++) {
                int col = no + 8 * j + 2 * c0;
                float v0 = fmaxf(acc[i][j][2 * rr + 0] + sbias[col + 0], 0.f);
                float v1 = fmaxf(acc[i][j][2 * rr + 1] + sbias[col + 1], 0.f);
                *(float2*)&g_hA[(size_t)row * HF + col] = make_float2(v0, v1);
                __half2 h2 = __floats2half2_rn(dv * v0, dv * v1);
                *reinterpret_cast<__half2*>(&g_fA[(size_t)row * HF + col]) = h2;
            }
        }
    }
}

// ---------------- fused hop kernel ------------------------------------------
// warp per dst node. fp16 shadow stores p[n] = dinv[n]*h[n]:
//   agg[d] = dinv[d] * sum_{s in N(d)} p[s] + dinv[d]^2 * h[d]
// Full chunks fully unrolled; tail loop bounded (steps of 4, dummies -> row NN).
__global__ void __launch_bounds__(256, 4)
hop_kernel(int sel, float* __restrict__ dout,
           const float* __restrict__ biases, // [NHOPS, HF]
           const float* __restrict__ Watt,   // [NHOPS, 2*HF]
           const float* __restrict__ batt,   // [NHOPS]
           int hop)
{
    int warp = (blockIdx.x * blockDim.x + threadIdx.x) >> 5;
    int lane = threadIdx.x & 31;
    if (warp >= NN) return;

    const float*  hin   = (sel == 0) ? g_hA : g_hB;
    const __half* fin   = (sel == 0) ? g_fA : g_fB;
    float*        hout  = (sel == 0) ? g_hB : ((sel == 1) ? g_hA : dout);
    __half*       fout  = (sel == 0) ? g_fB : g_fA;   // unused when sel==2

    const float4* hin4 = (const float4*)hin;
    const uint2*  fin2 = (const uint2*)fin;           // 4 halves per lane

    int rowbase = warp * 32;                          // 32-bit index math
    float4 hd = hin4[rowbase + lane];                 // own row, fp32 (exact)

    float dv = g_dinv[warp];
    float d2 = dv * dv;
    float4 acc = make_float4(0.f, 0.f, 0.f, 0.f);     // sum of p[s]

    auto gather4 = [&](int ed, int j) {
        int s0 = __shfl_sync(0xffffffffu, ed, j + 0);
        int s1 = __shfl_sync(0xffffffffu, ed, j + 1);
        int s2 = __shfl_sync(0xffffffffu, ed, j + 2);
        int s3 = __shfl_sync(0xffffffffu, ed, j + 3);
        uint2 r0 = fin2[s0 * 32 + lane];
        uint2 r1 = fin2[s1 * 32 + lane];
        uint2 r2 = fin2[s2 * 32 + lane];
        uint2 r3 = fin2[s3 * 32 + lane];
        float4 f0 = cvt16(r0), f1 = cvt16(r1), f2 = cvt16(r2), f3 = cvt16(r3);
        acc.x += (f0.x + f1.x) + (f2.x + f3.x);
        acc.y += (f0.y + f1.y) + (f2.y + f3.y);
        acc.z += (f0.z + f1.z) + (f2.z + f3.z);
        acc.w += (f0.w + f1.w) + (f2.w + f3.w);
    };

    int beg = g_rowptr[warp], end = g_rowptr[warp + 1];
    int c = beg;
#pragma unroll 1
    for (; c + 32 <= end; c += 32) {
        int ed = g_col[c + lane];
#pragma unroll
        for (int j = 0; j < 32; j += 4) gather4(ed, j);
    }
    int rem = end - c;                                // 0..31
    if (rem) {
        int ed = (lane < rem) ? g_col[c + lane] : NN; // dummies -> zero row
#pragma unroll 2
        for (int j = 0; j < rem; j += 4) gather4(ed, j);
    }

    float4 b4 = ((const float4*)(biases + hop * HF))[lane];
    float4 hk;
    hk.x = fmaxf(fmaf(dv, acc.x, fmaf(d2, hd.x, b4.x)), 0.f);
    hk.y = fmaxf(fmaf(dv, acc.y, fmaf(d2, hd.y, b4.y)), 0.f);
    hk.z = fmaxf(fmaf(dv, acc.z, fmaf(d2, hd.z, b4.z)), 0.f);
    hk.w = fmaxf(fmaf(dv, acc.w, fmaf(d2, hd.w, b4.w)), 0.f);

    float4 wk = ((const float4*)(Watt + hop * 2 * HF))[lane];
    float4 wh = ((const float4*)(Watt + hop * 2 * HF + HF))[lane];
    float part = hk.x * wk.x + hk.y * wk.y + hk.z * wk.z + hk.w * wk.w
               + hd.x * wh.x + hd.y * wh.y + hd.z * wh.z + hd.w * wh.w;
#pragma unroll
    for (int off = 16; off; off >>= 1)
        part += __shfl_xor_sync(0xffffffffu, part, off);

    float a = tanhf(part + batt[hop]);
    float4 o;
    o.x = a * hk.x + (1.f - a) * hd.x;
    o.y = a * hk.y + (1.f - a) * hd.y;
    o.z = a * hk.z + (1.f - a) * hd.z;
    o.w = a * hk.w + (1.f - a) * hd.w;
    ((float4*)hout)[rowbase + lane] = o;
    if (sel != 2) {
        __half2 p0 = __floats2half2_rn(dv * o.x, dv * o.y);
        __half2 p1 = __floats2half2_rn(dv * o.z, dv * o.w);
        uint2 pk;
        pk.x = *reinterpret_cast<unsigned*>(&p0);
        pk.y = *reinterpret_cast<unsigned*>(&p1);
        ((uint2*)fout)[rowbase + lane] = pk;
    }
}

// ---------------- launch ------------------------------------------------------
static cudaStream_t g_s2 = nullptr;
static cudaEvent_t  g_ev1 = nullptr, g_ev2 = nullptr;

extern "C" void kernel_launch(void* const* d_in, const int* in_sizes, int n_in,
                              void* d_out, int out_size)
{
    const int*   ei       = (const int*)d_in[0];     // [2, E]
    const float* features = (const float*)d_in[1];   // [N, 256]
    const float* W0       = (const float*)d_in[2];   // [256, 128]
    const float* b0       = (const float*)d_in[3];   // [128]
    const float* biases   = (const float*)d_in[4];   // [4, 128]
    const float* Watt     = (const float*)d_in[5];   // [4, 256]
    const float* batt     = (const float*)d_in[6];   // [4]
    float* out = (float*)d_out;

    const int* src = ei;
    const int* dst = ei + EE;

    if (!g_s2) {   // host-side infra handles, created once (no device memory)
        cudaStreamCreateWithFlags(&g_s2, cudaStreamNonBlocking);
        cudaEventCreateWithFlags(&g_ev1, cudaEventDisableTiming);
        cudaEventCreateWithFlags(&g_ev2, cudaEventDisableTiming);
    }

    const int TB = 256;
    int nBlocksE = (EE + TB - 1) / TB;
    int nbScan   = (NN + 1023) / 1024;

    // zero g_deg via memset node
    void* degPtr = nullptr;
    cudaGetSymbolAddress(&degPtr, g_deg);
    cudaMemsetAsync(degPtr, 0, NN * sizeof(int));

    // CSR build chain on the capture (default) stream
    hist_kernel<<<nBlocksE, TB>>>(dst);
    scan1_kernel<<<nbScan, 1024>>>();
    cudaEventRecord(g_ev1);                          // dinv ready

    // GEMM forks off: depends only on dinv, overlaps scan23+scatter
    cudaStreamWaitEvent(g_s2, g_ev1, 0);
    gemm_relu_kernel<<<(NN + 127) / 128, 256, 0, g_s2>>>(features, W0, b0);
    cudaEventRecord(g_ev2, g_s2);

    scan23_kernel<<<nbScan, 1024>>>();
    scatter_kernel<<<nBlocksE, TB>>>(src, dst);

    cudaStreamWaitEvent(0, g_ev2, 0);                // join before hops

    // 4 fused hops, ping-pong, last hop writes d_out
    int hopBlocks = (NN * 32 + TB - 1) / TB;         // warp per node
    hop_kernel<<<hopBlocks, TB>>>(0, out, biases, Watt, batt, 0); // A -> B
    hop_kernel<<<hopBlocks, TB>>>(1, out, biases, Watt, batt, 1); // B -> A
    hop_kernel<<<hopBlocks, TB>>>(0, out, biases, Watt, batt, 2); // A -> B
    hop_kernel<<<hopBlocks, TB>>>(2, out, biases, Watt, batt, 3); // B -> out
}